// round 1
// baseline (speedup 1.0000x reference)
#include <cuda_runtime.h>
#include <cuda_bf16.h>
#include <math.h>

#define TMAXV 1024
#define BATCH 2
#define EMB   768
#define NH    12
#define HD    64
#define NL    12
#define VOC   50257
#define ROWS  (BATCH*TMAXV)   // 2048

// ---------------- scratch (device globals, no allocation) ----------------
__device__ float g_x  [ROWS*EMB];
__device__ float g_h  [ROWS*EMB];
__device__ float g_qkv[ROWS*3*EMB];
__device__ float g_att[ROWS*EMB];
__device__ float g_mlp[ROWS*4*EMB];

// ---------------- embedding ----------------
__global__ void embed_kernel(const int* __restrict__ idx, const float* __restrict__ wte,
                             const float* __restrict__ wpe, float* __restrict__ x) {
    int row = blockIdx.x;
    int t   = row % TMAXV;
    int tok = idx[row];
    const float* we = wte + (size_t)tok * EMB;
    const float* pe = wpe + (size_t)t   * EMB;
    float* xr = x + (size_t)row * EMB;
    for (int e = threadIdx.x; e < EMB; e += blockDim.x)
        xr[e] = we[e] + pe[e];
}

// ---------------- layernorm (block per row, 256 threads, E=768) ----------------
__global__ __launch_bounds__(256)
void ln_kernel(const float* __restrict__ x, const float* __restrict__ w,
               const float* __restrict__ b, float* __restrict__ out) {
    int row = blockIdx.x;
    const float* xr = x + (size_t)row * EMB;
    int tid = threadIdx.x;
    float v0 = xr[tid], v1 = xr[tid + 256], v2 = xr[tid + 512];
    float s  = v0 + v1 + v2;
    float sq = v0*v0 + v1*v1 + v2*v2;
    __shared__ float sh_s[8], sh_q[8];
    #pragma unroll
    for (int o = 16; o; o >>= 1) {
        s  += __shfl_xor_sync(0xffffffffu, s,  o);
        sq += __shfl_xor_sync(0xffffffffu, sq, o);
    }
    int wid = tid >> 5, ln = tid & 31;
    if (ln == 0) { sh_s[wid] = s; sh_q[wid] = sq; }
    __syncthreads();
    s = 0.f; sq = 0.f;
    #pragma unroll
    for (int i = 0; i < 8; i++) { s += sh_s[i]; sq += sh_q[i]; }
    float mean = s * (1.f / EMB);
    float var  = sq * (1.f / EMB) - mean * mean;
    float rstd = rsqrtf(var + 1e-5f);
    float* orow = out + (size_t)row * EMB;
    orow[tid]       = (v0 - mean) * rstd * w[tid]       + b[tid];
    orow[tid + 256] = (v1 - mean) * rstd * w[tid + 256] + b[tid + 256];
    orow[tid + 512] = (v2 - mean) * rstd * w[tid + 512] + b[tid + 512];
}

// ---------------- GEMM: C[M,N] = A[M,K] @ B (+bias)(+gelu)(+res) ----------------
// BT=false: B is [K,N] row-major.  BT=true: B is [N,K] row-major (B^T applied).
__device__ __forceinline__ float gelu_f(float v) {
    float u = 0.7978845608028654f * (v + 0.044715f * v * v * v);
    return 0.5f * v * (1.f + tanhf(u));
}

template<bool BT, bool DOGELU>
__global__ __launch_bounds__(256, 2)
void gemm_kernel(const float* __restrict__ A, const float* __restrict__ B,
                 const float* __restrict__ bias, const float* __restrict__ res,
                 float* __restrict__ C, int M, int N, int K) {
    __shared__ __align__(16) float As[2][8][128];
    __shared__ __align__(16) float Bs[2][8][128];
    int tid = threadIdx.x;
    int tx = tid & 15, ty = tid >> 4;
    int bx = blockIdx.x, by = blockIdx.y;

    // A tile loader: 128 rows x 8 k, one float4 per thread
    int am = tid >> 1;
    int ak = (tid & 1) << 2;
    const float* Aptr = A + (size_t)(by * 128 + am) * K + ak;

    int bkl, bnl;
    const float* Bptr;
    bool bvalid = true;
    if (BT) {
        bnl = tid >> 1;
        bkl = (tid & 1) << 2;
        int gn = bx * 128 + bnl;
        bvalid = (gn < N);
        Bptr = B + (size_t)(bvalid ? gn : 0) * K + bkl;
    } else {
        bkl = tid >> 5;
        bnl = (tid & 31) << 2;
        Bptr = B + (size_t)bkl * N + bx * 128 + bnl;
    }

    float acc[8][8];
    #pragma unroll
    for (int i = 0; i < 8; i++)
        #pragma unroll
        for (int j = 0; j < 8; j++) acc[i][j] = 0.f;

    int KT = K >> 3;

    auto load_tile = [&](int kt, int buf) {
        float4 av = *(const float4*)(Aptr + kt * 8);
        As[buf][ak + 0][am] = av.x; As[buf][ak + 1][am] = av.y;
        As[buf][ak + 2][am] = av.z; As[buf][ak + 3][am] = av.w;
        if (BT) {
            float4 bv = bvalid ? *(const float4*)(Bptr + kt * 8)
                               : make_float4(0.f, 0.f, 0.f, 0.f);
            Bs[buf][bkl + 0][bnl] = bv.x; Bs[buf][bkl + 1][bnl] = bv.y;
            Bs[buf][bkl + 2][bnl] = bv.z; Bs[buf][bkl + 3][bnl] = bv.w;
        } else {
            float4 bv = *(const float4*)(Bptr + (size_t)kt * 8 * N);
            *(float4*)&Bs[buf][bkl][bnl] = bv;
        }
    };

    load_tile(0, 0);
    __syncthreads();

    for (int kt = 0; kt < KT; kt++) {
        int cur = kt & 1;
        if (kt + 1 < KT) load_tile(kt + 1, cur ^ 1);
        #pragma unroll
        for (int kk = 0; kk < 8; kk++) {
            float4 a0 = *(const float4*)&As[cur][kk][ty * 4];
            float4 a1 = *(const float4*)&As[cur][kk][64 + ty * 4];
            float4 b0 = *(const float4*)&Bs[cur][kk][tx * 4];
            float4 b1 = *(const float4*)&Bs[cur][kk][64 + tx * 4];
            float av[8] = {a0.x, a0.y, a0.z, a0.w, a1.x, a1.y, a1.z, a1.w};
            float bv[8] = {b0.x, b0.y, b0.z, b0.w, b1.x, b1.y, b1.z, b1.w};
            #pragma unroll
            for (int i = 0; i < 8; i++)
                #pragma unroll
                for (int j = 0; j < 8; j++)
                    acc[i][j] += av[i] * bv[j];
        }
        __syncthreads();
    }

    // epilogue
    int colg[8]; float bb[8];
    #pragma unroll
    for (int j = 0; j < 8; j++) {
        int cj = (j < 4) ? tx * 4 + j : 64 + tx * 4 + (j - 4);
        colg[j] = bx * 128 + cj;
        bb[j] = (bias != nullptr && colg[j] < N) ? bias[colg[j]] : 0.f;
    }
    #pragma unroll
    for (int i = 0; i < 8; i++) {
        int ri = (i < 4) ? ty * 4 + i : 64 + ty * 4 + (i - 4);
        int gr = by * 128 + ri;
        const float* rrow = res ? res + (size_t)gr * N : nullptr;
        float* crow = C + (size_t)gr * N;
        #pragma unroll
        for (int j = 0; j < 8; j++) {
            if (colg[j] < N) {
                float c = acc[i][j] + bb[j];
                if (DOGELU) c = gelu_f(c);
                if (res) c += rrow[colg[j]];
                crow[colg[j]] = c;
            }
        }
    }
}

// ---------------- fused causal flash attention ----------------
// grid (T/8, H, B), 256 thr = 8 warps, warp = one query. qkv row: [q(768) k(768) v(768)]
__global__ __launch_bounds__(256)
void attn_kernel(const float* __restrict__ qkv, float* __restrict__ out) {
    __shared__ __align__(16) float Ks[64][68];
    __shared__ __align__(16) float Vs[64][68];
    __shared__ __align__(16) float Ps[8][64];
    int b  = blockIdx.z, hh = blockIdx.y;
    int q0 = blockIdx.x << 3;
    int w = threadIdx.x >> 5, lane = threadIdx.x & 31;
    int q = q0 + w;

    const float* qrow = qkv + (size_t)(b * TMAXV + q) * (3 * EMB) + hh * HD;
    float qreg[64];
    #pragma unroll
    for (int d = 0; d < 64; d += 4) {
        float4 qv = *(const float4*)(qrow + d);
        qreg[d] = qv.x * 0.125f; qreg[d + 1] = qv.y * 0.125f;
        qreg[d + 2] = qv.z * 0.125f; qreg[d + 3] = qv.w * 0.125f;
    }

    float m = -1e30f, ssum = 0.f, o0 = 0.f, o1 = 0.f;
    int ntiles = (q0 >> 6) + 1;
    int lr = threadIdx.x >> 4;         // 0..15
    int ld = (threadIdx.x & 15) << 2;  // 0..60

    for (int kt = 0; kt < ntiles; kt++) {
        int k0 = kt << 6;
        #pragma unroll
        for (int rr = 0; rr < 64; rr += 16) {
            const float* kr = qkv + (size_t)(b * TMAXV + k0 + lr + rr) * (3 * EMB) + hh * HD;
            *(float4*)&Ks[lr + rr][ld] = *(const float4*)(kr + EMB     + ld);
            *(float4*)&Vs[lr + rr][ld] = *(const float4*)(kr + 2 * EMB + ld);
        }
        __syncthreads();

        float s0 = 0.f, s1 = 0.f;
        #pragma unroll
        for (int d = 0; d < 64; d += 4) {
            float4 k0v = *(const float4*)&Ks[lane][d];
            float4 k1v = *(const float4*)&Ks[lane + 32][d];
            s0 += qreg[d] * k0v.x + qreg[d+1] * k0v.y + qreg[d+2] * k0v.z + qreg[d+3] * k0v.w;
            s1 += qreg[d] * k1v.x + qreg[d+1] * k1v.y + qreg[d+2] * k1v.z + qreg[d+3] * k1v.w;
        }
        if (k0 + lane      > q) s0 = -1e30f;
        if (k0 + lane + 32 > q) s1 = -1e30f;

        float tmax = fmaxf(s0, s1);
        #pragma unroll
        for (int o = 16; o; o >>= 1)
            tmax = fmaxf(tmax, __shfl_xor_sync(0xffffffffu, tmax, o));
        float mnew  = fmaxf(m, tmax);
        float alpha = __expf(m - mnew);
        float p0 = __expf(s0 - mnew);
        float p1 = __expf(s1 - mnew);
        float ps = p0 + p1;
        #pragma unroll
        for (int o = 16; o; o >>= 1)
            ps += __shfl_xor_sync(0xffffffffu, ps, o);
        ssum = ssum * alpha + ps;
        o0 *= alpha; o1 *= alpha;
        m = mnew;

        Ps[w][lane] = p0; Ps[w][lane + 32] = p1;
        __syncwarp();
        #pragma unroll
        for (int k4 = 0; k4 < 64; k4 += 4) {
            float4 pv = *(const float4*)&Ps[w][k4];
            float2 v0 = *(const float2*)&Vs[k4 + 0][lane << 1];
            float2 v1 = *(const float2*)&Vs[k4 + 1][lane << 1];
            float2 v2 = *(const float2*)&Vs[k4 + 2][lane << 1];
            float2 v3 = *(const float2*)&Vs[k4 + 3][lane << 1];
            o0 += pv.x * v0.x + pv.y * v1.x + pv.z * v2.x + pv.w * v3.x;
            o1 += pv.x * v0.y + pv.y * v1.y + pv.z * v2.y + pv.w * v3.y;
        }
        __syncthreads();
    }

    float inv = 1.f / ssum;
    float2 ov = make_float2(o0 * inv, o1 * inv);
    *(float2*)(out + (size_t)(b * TMAXV + q) * EMB + hh * HD + (lane << 1)) = ov;
}

// ---------------- host orchestration ----------------
extern "C" void kernel_launch(void* const* d_in, const int* in_sizes, int n_in,
                              void* d_out, int out_size) {
    const int*   idx         = (const int*)  d_in[0];
    const float* wte         = (const float*)d_in[1];
    const float* wpe         = (const float*)d_in[2];
    const float* ln1_w       = (const float*)d_in[3];
    const float* ln1_b       = (const float*)d_in[4];
    const float* attn_w      = (const float*)d_in[5];
    const float* attn_b      = (const float*)d_in[6];
    const float* attn_proj_w = (const float*)d_in[7];
    const float* attn_proj_b = (const float*)d_in[8];
    const float* ln2_w       = (const float*)d_in[9];
    const float* ln2_b       = (const float*)d_in[10];
    const float* fc_w        = (const float*)d_in[11];
    const float* fc_b        = (const float*)d_in[12];
    const float* fc_proj_w   = (const float*)d_in[13];
    const float* fc_proj_b   = (const float*)d_in[14];
    const float* lnf_w       = (const float*)d_in[15];
    const float* lnf_b       = (const float*)d_in[16];

    float *x, *h, *qkvb, *attb, *mlpb;
    cudaGetSymbolAddress((void**)&x,    g_x);
    cudaGetSymbolAddress((void**)&h,    g_h);
    cudaGetSymbolAddress((void**)&qkvb, g_qkv);
    cudaGetSymbolAddress((void**)&attb, g_att);
    cudaGetSymbolAddress((void**)&mlpb, g_mlp);

    embed_kernel<<<ROWS, 256>>>(idx, wte, wpe, x);

    for (int l = 0; l < NL; l++) {
        ln_kernel<<<ROWS, 256>>>(x, ln1_w + l * EMB, ln1_b + l * EMB, h);
        gemm_kernel<false, false><<<dim3(18, 16), 256>>>(
            h, attn_w + (size_t)l * EMB * 3 * EMB, attn_b + (size_t)l * 3 * EMB,
            nullptr, qkvb, ROWS, 3 * EMB, EMB);
        attn_kernel<<<dim3(TMAXV / 8, NH, BATCH), 256>>>(qkvb, attb);
        gemm_kernel<false, false><<<dim3(6, 16), 256>>>(
            attb, attn_proj_w + (size_t)l * EMB * EMB, attn_proj_b + (size_t)l * EMB,
            x, x, ROWS, EMB, EMB);
        ln_kernel<<<ROWS, 256>>>(x, ln2_w + l * EMB, ln2_b + l * EMB, h);
        gemm_kernel<false, true><<<dim3(24, 16), 256>>>(
            h, fc_w + (size_t)l * EMB * 4 * EMB, fc_b + (size_t)l * 4 * EMB,
            nullptr, mlpb, ROWS, 4 * EMB, EMB);
        gemm_kernel<false, false><<<dim3(6, 16), 256>>>(
            mlpb, fc_proj_w + (size_t)l * 4 * EMB * EMB, fc_proj_b + (size_t)l * EMB,
            x, x, ROWS, EMB, 4 * EMB);
    }

    ln_kernel<<<ROWS, 256>>>(x, lnf_w, lnf_b, h);
    gemm_kernel<true, false><<<dim3((VOC + 127) / 128, 16), 256>>>(
        h, wte, nullptr, nullptr, (float*)d_out, ROWS, VOC, EMB);
}

// round 4
// speedup vs baseline: 1.8159x; 1.8159x over previous
#include <cuda_runtime.h>
#include <cuda_bf16.h>
#include <cstdint>
#include <math.h>

#define TMAXV 1024
#define BATCH 2
#define EMB   768
#define NH    12
#define HD    64
#define NL    12
#define VOC   50257
#define ROWS  (BATCH*TMAXV)   // 2048

// ---------------- scratch (device globals, no allocation) ----------------
__device__ __align__(256) float g_x  [ROWS*EMB];
__device__ __align__(256) float g_h  [ROWS*EMB];
__device__ __align__(256) float g_qkv[ROWS*3*EMB];
__device__ __align__(256) float g_att[ROWS*EMB];
__device__ __align__(256) float g_mlp[ROWS*4*EMB];
__device__ __align__(256) __nv_bfloat16 g_abf [ROWS*2*4*EMB];
__device__ __align__(256) __nv_bfloat16 g_wbf [3*EMB*2*4*EMB];
__device__ __align__(256) __nv_bfloat16 g_wtebf[(size_t)VOC*2*EMB];

// ======================= PTX helpers (baseline PTX only, sm_80+ features) =======================
__device__ __forceinline__ uint32_t smem_to_u32(const void* p) {
    uint32_t a;
    asm("{ .reg .u64 t; cvta.to.shared.u64 t, %1; cvt.u32.u64 %0, t; }" : "=r"(a) : "l"(p));
    return a;
}
__device__ __forceinline__ void cp_async16(uint32_t saddr, const void* gaddr) {
    asm volatile("cp.async.cg.shared.global [%0], [%1], 16;" :: "r"(saddr), "l"(gaddr));
}
__device__ __forceinline__ void cp_commit() { asm volatile("cp.async.commit_group;"); }
__device__ __forceinline__ void cp_wait0()  { asm volatile("cp.async.wait_group 0;"); }
__device__ __forceinline__ void ldsm4(uint32_t& r0, uint32_t& r1, uint32_t& r2, uint32_t& r3, uint32_t addr) {
    asm volatile("ldmatrix.sync.aligned.m8n8.x4.shared.b16 {%0,%1,%2,%3}, [%4];"
        : "=r"(r0), "=r"(r1), "=r"(r2), "=r"(r3) : "r"(addr));
}
__device__ __forceinline__ void mma16816(float* d, const uint32_t* a, const uint32_t* b) {
    asm volatile("mma.sync.aligned.m16n8k16.row.col.f32.bf16.bf16.f32 "
        "{%0,%1,%2,%3}, {%4,%5,%6,%7}, {%8,%9}, {%0,%1,%2,%3};"
        : "+f"(d[0]), "+f"(d[1]), "+f"(d[2]), "+f"(d[3])
        : "r"(a[0]), "r"(a[1]), "r"(a[2]), "r"(a[3]), "r"(b[0]), "r"(b[1]));
}

// ---------------- embedding ----------------
__global__ void embed_kernel(const int* __restrict__ idx, const float* __restrict__ wte,
                             const float* __restrict__ wpe, float* __restrict__ x) {
    int row = blockIdx.x;
    int t   = row % TMAXV;
    int tok = idx[row];
    const float* we = wte + (size_t)tok * EMB;
    const float* pe = wpe + (size_t)t   * EMB;
    float* xr = x + (size_t)row * EMB;
    for (int e = threadIdx.x; e < EMB; e += blockDim.x)
        xr[e] = we[e] + pe[e];
}

// ---------------- layernorm ----------------
__global__ __launch_bounds__(256)
void ln_kernel(const float* __restrict__ x, const float* __restrict__ w,
               const float* __restrict__ b, float* __restrict__ out) {
    int row = blockIdx.x;
    const float* xr = x + (size_t)row * EMB;
    int tid = threadIdx.x;
    float v0 = xr[tid], v1 = xr[tid + 256], v2 = xr[tid + 512];
    float s  = v0 + v1 + v2;
    float sq = v0*v0 + v1*v1 + v2*v2;
    __shared__ float sh_s[8], sh_q[8];
    #pragma unroll
    for (int o = 16; o; o >>= 1) {
        s  += __shfl_xor_sync(0xffffffffu, s,  o);
        sq += __shfl_xor_sync(0xffffffffu, sq, o);
    }
    int wid = tid >> 5, ln = tid & 31;
    if (ln == 0) { sh_s[wid] = s; sh_q[wid] = sq; }
    __syncthreads();
    s = 0.f; sq = 0.f;
    #pragma unroll
    for (int i = 0; i < 8; i++) { s += sh_s[i]; sq += sh_q[i]; }
    float mean = s * (1.f / EMB);
    float var  = sq * (1.f / EMB) - mean * mean;
    float rstd = rsqrtf(var + 1e-5f);
    float* orow = out + (size_t)row * EMB;
    orow[tid]       = (v0 - mean) * rstd * w[tid]       + b[tid];
    orow[tid + 256] = (v1 - mean) * rstd * w[tid + 256] + b[tid + 256];
    orow[tid + 512] = (v2 - mean) * rstd * w[tid + 512] + b[tid + 512];
}

// ---------------- split-bf16 conversions ----------------
// [M,K] f32 -> [M,2K] bf16 (hi | lo)
__global__ __launch_bounds__(256)
void conva_kernel(const float* __restrict__ in, __nv_bfloat16* __restrict__ out, int K) {
    int row = blockIdx.x;
    const float* ir = in + (size_t)row * K;
    __nv_bfloat16* orow = out + (size_t)row * 2 * K;
    for (int k = threadIdx.x; k < K; k += 256) {
        float v = ir[k];
        __nv_bfloat16 hi = __float2bfloat16(v);
        float r = v - __bfloat162float(hi);
        orow[k]     = hi;
        orow[K + k] = __float2bfloat16(r);
    }
}

// weights: [K,N] f32 row-major -> [N,2K] bf16 (transpose + split)
__global__ __launch_bounds__(256)
void convw_kernel(const float* __restrict__ W, __nv_bfloat16* __restrict__ out, int K, int N) {
    __shared__ float t[32][33];
    int n0 = blockIdx.x * 32, k0 = blockIdx.y * 32;
    int tx = threadIdx.x & 31, ty = threadIdx.x >> 5;
    #pragma unroll
    for (int j = 0; j < 32; j += 8) {
        int k = k0 + ty + j, n = n0 + tx;
        t[ty + j][tx] = (n < N) ? W[(size_t)k * N + n] : 0.f;
    }
    __syncthreads();
    #pragma unroll
    for (int j = 0; j < 32; j += 8) {
        int n = n0 + ty + j, k = k0 + tx;
        if (n < N) {
            float v = t[tx][ty + j];
            __nv_bfloat16 hi = __float2bfloat16(v);
            float r = v - __bfloat162float(hi);
            out[(size_t)n * 2 * K + k]     = hi;
            out[(size_t)n * 2 * K + K + k] = __float2bfloat16(r);
        }
    }
}

// ---------------- mma.sync bf16 split GEMM ----------------
// C[M,N] = A[M,K] @ B[K,N] via 3 bf16 passes (hi*hi + lo*hi + hi*lo), fp32 register accum.
// Ab: [M,2K] bf16 (hi|lo), Bb: [N,2K] bf16 (hi|lo, K-major).
// CTA tile 128x128, BK=32, 8 warps (2m x 4n), warp tile 64x32, cp.async double buffer.
__device__ __forceinline__ float gelu_f(float v) {
    float u = 0.7978845608028654f * (v + 0.044715f * v * v * v);
    return 0.5f * v * (1.f + tanhf(u));
}

template<bool DOGELU, bool HASRES>
__global__ __launch_bounds__(256)
void gemm_mma_kernel(const __nv_bfloat16* __restrict__ Ab, const __nv_bfloat16* __restrict__ Bb,
                     const float* __restrict__ bias, const float* __restrict__ res,
                     float* __restrict__ C, int N, int K) {
    __shared__ __align__(128) uint8_t smem[2][16384];   // per stage: A 8KB + B 8KB
    const int tid  = threadIdx.x;
    const int lane = tid & 31, wid = tid >> 5;
    const int wm = wid >> 2, wn = wid & 3;              // 2 x 4 warp grid
    const int mt = blockIdx.x, nt = blockIdx.y;
    const size_t K2 = (size_t)2 * K;
    const uint32_t sbase = smem_to_u32(smem);

    // per-thread global-load coords (16B vectors)
    const int lrow = tid >> 2;      // 0..63 (+64 on 2nd vec)
    const int lch  = tid & 3;       // 16B chunk within 64B row
    const __nv_bfloat16* Agbase = Ab + (size_t)(mt * 128) * K2;

    // ldmatrix lane-address components (stage-independent)
    const int arow = wm * 64 + (lane & 15);
    const uint32_t asw_base = (uint32_t)((arow >> 1) & 3);
    const uint32_t aoff_lm  = (uint32_t)(arow * 64);
    const int brow = wn * 32 + (lane & 7) + ((lane >> 4) << 3);
    const uint32_t bsw_base = (uint32_t)((brow >> 1) & 3);
    const uint32_t boff_lm  = (uint32_t)(brow * 64);
    const uint32_t a_chsel  = (uint32_t)(lane >> 4);        // 0/1
    const uint32_t b_chsel  = (uint32_t)((lane >> 3) & 1);  // 0/1

    float acc[4][4][4];
    #pragma unroll
    for (int i = 0; i < 4; i++)
        #pragma unroll
        for (int j = 0; j < 4; j++)
            #pragma unroll
            for (int e = 0; e < 4; e++) acc[i][j][e] = 0.f;

    const int KC = K >> 5;      // k32-chunks per pass
    const int NC = 3 * KC;      // total chunks (3 passes)

    auto load_chunk = [&](int c, int stg) {
        int p  = c / KC;
        int kk = c - p * KC;
        int aoff = ((p == 1) ? K : 0) + kk * 32;
        int boff = ((p == 2) ? K : 0) + kk * 32;
        uint32_t sA = sbase + stg * 16384;
        uint32_t sB = sA + 8192;
        #pragma unroll
        for (int i = 0; i < 2; i++) {
            int row = lrow + 64 * i;
            const void* g = Agbase + (size_t)row * K2 + aoff + lch * 8;
            uint32_t d = sA + row * 64 + (((uint32_t)lch ^ ((uint32_t)(row >> 1) & 3)) << 4);
            cp_async16(d, g);
        }
        #pragma unroll
        for (int i = 0; i < 2; i++) {
            int row = lrow + 64 * i;
            int gn = nt * 128 + row;
            if (gn >= N) gn = N - 1;
            const void* g = Bb + (size_t)gn * K2 + boff + lch * 8;
            uint32_t d = sB + row * 64 + (((uint32_t)lch ^ ((uint32_t)(row >> 1) & 3)) << 4);
            cp_async16(d, g);
        }
        cp_commit();
    };

    load_chunk(0, 0);

    for (int c = 0; c < NC; c++) {
        int stg = c & 1;
        cp_wait0();
        __syncthreads();
        if (c + 1 < NC) load_chunk(c + 1, stg ^ 1);

        uint32_t sA = sbase + stg * 16384;
        uint32_t sB = sA + 8192;
        #pragma unroll
        for (int s = 0; s < 2; s++) {
            uint32_t aswz = ((2u * s + a_chsel) ^ asw_base) << 4;
            uint32_t bswz = ((2u * s + b_chsel) ^ bsw_base) << 4;
            uint32_t a[4][4], b[2][4];
            #pragma unroll
            for (int mi = 0; mi < 4; mi++)
                ldsm4(a[mi][0], a[mi][1], a[mi][2], a[mi][3], sA + aoff_lm + mi * 1024 + aswz);
            #pragma unroll
            for (int j = 0; j < 2; j++)
                ldsm4(b[j][0], b[j][1], b[j][2], b[j][3], sB + boff_lm + j * 1024 + bswz);
            #pragma unroll
            for (int mi = 0; mi < 4; mi++) {
                #pragma unroll
                for (int nj = 0; nj < 4; nj++)
                    mma16816(acc[mi][nj], a[mi], &b[nj >> 1][(nj & 1) * 2]);
            }
        }
    }
    __syncthreads();

    // ---------------- epilogue ----------------
    const int rowbase = mt * 128 + wm * 64 + (lane >> 2);
    const int cbase   = nt * 128 + wn * 32 + (lane & 3) * 2;
    const bool vec_ok = ((N & 1) == 0);   // odd N (lm_head): rows only 4B-aligned
    float bb0[4], bb1[4];
    #pragma unroll
    for (int nj = 0; nj < 4; nj++) {
        int cc = cbase + nj * 8;
        bb0[nj] = (bias != nullptr && cc     < N) ? bias[cc]     : 0.f;
        bb1[nj] = (bias != nullptr && cc + 1 < N) ? bias[cc + 1] : 0.f;
    }
    #pragma unroll
    for (int mi = 0; mi < 4; mi++) {
        #pragma unroll
        for (int h = 0; h < 2; h++) {
            int rr = rowbase + mi * 16 + 8 * h;
            float* crow = C + (size_t)rr * N;
            const float* rrow = HASRES ? res + (size_t)rr * N : nullptr;
            #pragma unroll
            for (int nj = 0; nj < 4; nj++) {
                int cc = cbase + nj * 8;
                float v0 = acc[mi][nj][2 * h + 0] + bb0[nj];
                float v1 = acc[mi][nj][2 * h + 1] + bb1[nj];
                if (DOGELU) { v0 = gelu_f(v0); v1 = gelu_f(v1); }
                if (cc + 1 < N) {
                    if (HASRES) { v0 += rrow[cc]; v1 += rrow[cc + 1]; }
                    if (vec_ok) {
                        *(float2*)&crow[cc] = make_float2(v0, v1);
                    } else {
                        crow[cc]     = v0;
                        crow[cc + 1] = v1;
                    }
                } else if (cc < N) {
                    if (HASRES) v0 += rrow[cc];
                    crow[cc] = v0;
                }
            }
        }
    }
}

// ---------------- fused causal flash attention ----------------
__global__ __launch_bounds__(256)
void attn_kernel(const float* __restrict__ qkv, float* __restrict__ out) {
    __shared__ __align__(16) float Ks[64][68];
    __shared__ __align__(16) float Vs[64][68];
    __shared__ __align__(16) float Ps[8][64];
    int b  = blockIdx.z, hh = blockIdx.y;
    int q0 = blockIdx.x << 3;
    int w = threadIdx.x >> 5, lane = threadIdx.x & 31;
    int q = q0 + w;

    const float* qrow = qkv + (size_t)(b * TMAXV + q) * (3 * EMB) + hh * HD;
    float qreg[64];
    #pragma unroll
    for (int d = 0; d < 64; d += 4) {
        float4 qv = *(const float4*)(qrow + d);
        qreg[d] = qv.x * 0.125f; qreg[d + 1] = qv.y * 0.125f;
        qreg[d + 2] = qv.z * 0.125f; qreg[d + 3] = qv.w * 0.125f;
    }

    float m = -1e30f, ssum = 0.f, o0 = 0.f, o1 = 0.f;
    int ntiles = (q0 >> 6) + 1;
    int lr = threadIdx.x >> 4;
    int ld = (threadIdx.x & 15) << 2;

    for (int kt = 0; kt < ntiles; kt++) {
        int k0 = kt << 6;
        #pragma unroll
        for (int rr = 0; rr < 64; rr += 16) {
            const float* kr = qkv + (size_t)(b * TMAXV + k0 + lr + rr) * (3 * EMB) + hh * HD;
            *(float4*)&Ks[lr + rr][ld] = *(const float4*)(kr + EMB     + ld);
            *(float4*)&Vs[lr + rr][ld] = *(const float4*)(kr + 2 * EMB + ld);
        }
        __syncthreads();

        float s0 = 0.f, s1 = 0.f;
        #pragma unroll
        for (int d = 0; d < 64; d += 4) {
            float4 k0v = *(const float4*)&Ks[lane][d];
            float4 k1v = *(const float4*)&Ks[lane + 32][d];
            s0 += qreg[d] * k0v.x + qreg[d+1] * k0v.y + qreg[d+2] * k0v.z + qreg[d+3] * k0v.w;
            s1 += qreg[d] * k1v.x + qreg[d+1] * k1v.y + qreg[d+2] * k1v.z + qreg[d+3] * k1v.w;
        }
        if (k0 + lane      > q) s0 = -1e30f;
        if (k0 + lane + 32 > q) s1 = -1e30f;

        float tmax = fmaxf(s0, s1);
        #pragma unroll
        for (int o = 16; o; o >>= 1)
            tmax = fmaxf(tmax, __shfl_xor_sync(0xffffffffu, tmax, o));
        float mnew  = fmaxf(m, tmax);
        float alpha = __expf(m - mnew);
        float p0 = __expf(s0 - mnew);
        float p1 = __expf(s1 - mnew);
        float ps = p0 + p1;
        #pragma unroll
        for (int o = 16; o; o >>= 1)
            ps += __shfl_xor_sync(0xffffffffu, ps, o);
        ssum = ssum * alpha + ps;
        o0 *= alpha; o1 *= alpha;
        m = mnew;

        Ps[w][lane] = p0; Ps[w][lane + 32] = p1;
        __syncwarp();
        #pragma unroll
        for (int k4 = 0; k4 < 64; k4 += 4) {
            float4 pv = *(const float4*)&Ps[w][k4];
            float2 v0 = *(const float2*)&Vs[k4 + 0][lane << 1];
            float2 v1 = *(const float2*)&Vs[k4 + 1][lane << 1];
            float2 v2 = *(const float2*)&Vs[k4 + 2][lane << 1];
            float2 v3 = *(const float2*)&Vs[k4 + 3][lane << 1];
            o0 += pv.x * v0.x + pv.y * v1.x + pv.z * v2.x + pv.w * v3.x;
            o1 += pv.x * v0.y + pv.y * v1.y + pv.z * v2.y + pv.w * v3.y;
        }
        __syncthreads();
    }

    float inv = 1.f / ssum;
    float2 ov = make_float2(o0 * inv, o1 * inv);
    *(float2*)(out + (size_t)(b * TMAXV + q) * EMB + hh * HD + (lane << 1)) = ov;
}

// ---------------- host orchestration ----------------
extern "C" void kernel_launch(void* const* d_in, const int* in_sizes, int n_in,
                              void* d_out, int out_size) {
    const int*   idx         = (const int*)  d_in[0];
    const float* wte         = (const float*)d_in[1];
    const float* wpe         = (const float*)d_in[2];
    const float* ln1_w       = (const float*)d_in[3];
    const float* ln1_b       = (const float*)d_in[4];
    const float* attn_w      = (const float*)d_in[5];
    const float* attn_b      = (const float*)d_in[6];
    const float* attn_proj_w = (const float*)d_in[7];
    const float* attn_proj_b = (const float*)d_in[8];
    const float* ln2_w       = (const float*)d_in[9];
    const float* ln2_b       = (const float*)d_in[10];
    const float* fc_w        = (const float*)d_in[11];
    const float* fc_b        = (const float*)d_in[12];
    const float* fc_proj_w   = (const float*)d_in[13];
    const float* fc_proj_b   = (const float*)d_in[14];
    const float* lnf_w       = (const float*)d_in[15];
    const float* lnf_b       = (const float*)d_in[16];

    float *x, *h, *qkvb, *attb, *mlpb;
    __nv_bfloat16 *abf, *wbf, *wtebf;
    cudaGetSymbolAddress((void**)&x,    g_x);
    cudaGetSymbolAddress((void**)&h,    g_h);
    cudaGetSymbolAddress((void**)&qkvb, g_qkv);
    cudaGetSymbolAddress((void**)&attb, g_att);
    cudaGetSymbolAddress((void**)&mlpb, g_mlp);
    cudaGetSymbolAddress((void**)&abf,  g_abf);
    cudaGetSymbolAddress((void**)&wbf,  g_wbf);
    cudaGetSymbolAddress((void**)&wtebf,g_wtebf);

    embed_kernel<<<ROWS, 256>>>(idx, wte, wpe, x);

    for (int l = 0; l < NL; l++) {
        // --- attention block ---
        ln_kernel<<<ROWS, 256>>>(x, ln1_w + l * EMB, ln1_b + l * EMB, h);
        conva_kernel<<<ROWS, 256>>>(h, abf, EMB);
        convw_kernel<<<dim3((3*EMB)/32, EMB/32), 256>>>(attn_w + (size_t)l * EMB * 3 * EMB, wbf, EMB, 3*EMB);
        gemm_mma_kernel<false,false><<<dim3(16, 18), 256>>>(
            abf, wbf, attn_b + (size_t)l * 3 * EMB, nullptr, qkvb, 3*EMB, EMB);

        attn_kernel<<<dim3(TMAXV / 8, NH, BATCH), 256>>>(qkvb, attb);

        conva_kernel<<<ROWS, 256>>>(attb, abf, EMB);
        convw_kernel<<<dim3(EMB/32, EMB/32), 256>>>(attn_proj_w + (size_t)l * EMB * EMB, wbf, EMB, EMB);
        gemm_mma_kernel<false,true><<<dim3(16, 6), 256>>>(
            abf, wbf, attn_proj_b + (size_t)l * EMB, x, x, EMB, EMB);

        // --- mlp block ---
        ln_kernel<<<ROWS, 256>>>(x, ln2_w + l * EMB, ln2_b + l * EMB, h);
        conva_kernel<<<ROWS, 256>>>(h, abf, EMB);
        convw_kernel<<<dim3((4*EMB)/32, EMB/32), 256>>>(fc_w + (size_t)l * EMB * 4 * EMB, wbf, EMB, 4*EMB);
        gemm_mma_kernel<true,false><<<dim3(16, 24), 256>>>(
            abf, wbf, fc_b + (size_t)l * 4 * EMB, nullptr, mlpb, 4*EMB, EMB);

        conva_kernel<<<ROWS, 256>>>(mlpb, abf, 4*EMB);
        convw_kernel<<<dim3(EMB/32, (4*EMB)/32), 256>>>(fc_proj_w + (size_t)l * 4 * EMB * EMB, wbf, 4*EMB, EMB);
        gemm_mma_kernel<false,true><<<dim3(16, 6), 256>>>(
            abf, wbf, fc_proj_b + (size_t)l * EMB, x, x, EMB, 4*EMB);
    }

    ln_kernel<<<ROWS, 256>>>(x, lnf_w, lnf_b, h);
    conva_kernel<<<ROWS, 256>>>(h, abf, EMB);
    conva_kernel<<<VOC, 256>>>(wte, wtebf, EMB);   // wte [V,E] row-major is already N-major
    gemm_mma_kernel<false,false><<<dim3(16, (VOC + 127) / 128), 256>>>(
        abf, wtebf, nullptr, nullptr, (float*)d_out, VOC, EMB);
}

// round 5
// speedup vs baseline: 2.1805x; 1.2008x over previous
#include <cuda_runtime.h>
#include <cuda_bf16.h>
#include <cstdint>
#include <math.h>

#define TMAXV 1024
#define BATCH 2
#define EMB   768
#define NH    12
#define HD    64
#define NL    12
#define VOC   50257
#define ROWS  (BATCH*TMAXV)   // 2048
#define BHT   (BATCH*NH)      // 24

// ---------------- scratch (device globals, no allocation) ----------------
__device__ __align__(256) float g_x  [ROWS*EMB];
__device__ __align__(256) float g_h  [ROWS*EMB];
__device__ __align__(256) float g_qkv[ROWS*3*EMB];
__device__ __align__(256) float g_att[ROWS*EMB];
__device__ __align__(256) float g_mlp[ROWS*4*EMB];
__device__ __align__(256) __nv_bfloat16 g_abf [ROWS*2*4*EMB];
__device__ __align__(256) __nv_bfloat16 g_wbf [3*EMB*2*4*EMB];
__device__ __align__(256) __nv_bfloat16 g_wtebf[(size_t)VOC*2*EMB];
// attention scratch
__device__ __align__(256) __nv_bfloat16 g_Qs[(size_t)BHT*TMAXV*2*HD];   // [bh][t][hi64|lo64]
__device__ __align__(256) __nv_bfloat16 g_Ks[(size_t)BHT*TMAXV*2*HD];
__device__ __align__(256) __nv_bfloat16 g_Vt[(size_t)BHT*HD*2*TMAXV];   // [bh][d][hiT|loT]
__device__ __align__(256) float         g_S [(size_t)BHT*TMAXV*TMAXV];  // 100MB
__device__ __align__(256) __nv_bfloat16 g_P [(size_t)BHT*TMAXV*2*TMAXV];// 100MB

// ======================= PTX helpers =======================
__device__ __forceinline__ uint32_t smem_to_u32(const void* p) {
    uint32_t a;
    asm("{ .reg .u64 t; cvta.to.shared.u64 t, %1; cvt.u32.u64 %0, t; }" : "=r"(a) : "l"(p));
    return a;
}
__device__ __forceinline__ void cp_async16(uint32_t saddr, const void* gaddr) {
    asm volatile("cp.async.cg.shared.global [%0], [%1], 16;" :: "r"(saddr), "l"(gaddr));
}
__device__ __forceinline__ void cp_commit() { asm volatile("cp.async.commit_group;"); }
__device__ __forceinline__ void cp_wait0()  { asm volatile("cp.async.wait_group 0;"); }
__device__ __forceinline__ void ldsm4(uint32_t& r0, uint32_t& r1, uint32_t& r2, uint32_t& r3, uint32_t addr) {
    asm volatile("ldmatrix.sync.aligned.m8n8.x4.shared.b16 {%0,%1,%2,%3}, [%4];"
        : "=r"(r0), "=r"(r1), "=r"(r2), "=r"(r3) : "r"(addr));
}
__device__ __forceinline__ void mma16816(float* d, const uint32_t* a, const uint32_t* b) {
    asm volatile("mma.sync.aligned.m16n8k16.row.col.f32.bf16.bf16.f32 "
        "{%0,%1,%2,%3}, {%4,%5,%6,%7}, {%8,%9}, {%0,%1,%2,%3};"
        : "+f"(d[0]), "+f"(d[1]), "+f"(d[2]), "+f"(d[3])
        : "r"(a[0]), "r"(a[1]), "r"(a[2]), "r"(a[3]), "r"(b[0]), "r"(b[1]));
}
__device__ __forceinline__ float gelu_f(float v) {
    float u = 0.7978845608028654f * (v + 0.044715f * v * v * v);
    return 0.5f * v * (1.f + tanhf(u));
}

// ---------------- embedding ----------------
__global__ void embed_kernel(const int* __restrict__ idx, const float* __restrict__ wte,
                             const float* __restrict__ wpe, float* __restrict__ x) {
    int row = blockIdx.x;
    int t   = row % TMAXV;
    int tok = idx[row];
    const float* we = wte + (size_t)tok * EMB;
    const float* pe = wpe + (size_t)t   * EMB;
    float* xr = x + (size_t)row * EMB;
    for (int e = threadIdx.x; e < EMB; e += blockDim.x)
        xr[e] = we[e] + pe[e];
}

// ---------------- layernorm ----------------
__global__ __launch_bounds__(256)
void ln_kernel(const float* __restrict__ x, const float* __restrict__ w,
               const float* __restrict__ b, float* __restrict__ out) {
    int row = blockIdx.x;
    const float* xr = x + (size_t)row * EMB;
    int tid = threadIdx.x;
    float v0 = xr[tid], v1 = xr[tid + 256], v2 = xr[tid + 512];
    float s  = v0 + v1 + v2;
    float sq = v0*v0 + v1*v1 + v2*v2;
    __shared__ float sh_s[8], sh_q[8];
    #pragma unroll
    for (int o = 16; o; o >>= 1) {
        s  += __shfl_xor_sync(0xffffffffu, s,  o);
        sq += __shfl_xor_sync(0xffffffffu, sq, o);
    }
    int wid = tid >> 5, ln = tid & 31;
    if (ln == 0) { sh_s[wid] = s; sh_q[wid] = sq; }
    __syncthreads();
    s = 0.f; sq = 0.f;
    #pragma unroll
    for (int i = 0; i < 8; i++) { s += sh_s[i]; sq += sh_q[i]; }
    float mean = s * (1.f / EMB);
    float var  = sq * (1.f / EMB) - mean * mean;
    float rstd = rsqrtf(var + 1e-5f);
    float* orow = out + (size_t)row * EMB;
    orow[tid]       = (v0 - mean) * rstd * w[tid]       + b[tid];
    orow[tid + 256] = (v1 - mean) * rstd * w[tid + 256] + b[tid + 256];
    orow[tid + 512] = (v2 - mean) * rstd * w[tid + 512] + b[tid + 512];
}

// ---------------- split-bf16 conversions ----------------
__global__ __launch_bounds__(256)
void conva_kernel(const float* __restrict__ in, __nv_bfloat16* __restrict__ out, int K) {
    int row = blockIdx.x;
    const float* ir = in + (size_t)row * K;
    __nv_bfloat16* orow = out + (size_t)row * 2 * K;
    for (int k = threadIdx.x; k < K; k += 256) {
        float v = ir[k];
        __nv_bfloat16 hi = __float2bfloat16(v);
        float r = v - __bfloat162float(hi);
        orow[k]     = hi;
        orow[K + k] = __float2bfloat16(r);
    }
}

__global__ __launch_bounds__(256)
void convw_kernel(const float* __restrict__ W, __nv_bfloat16* __restrict__ out, int K, int N) {
    __shared__ float t[32][33];
    int n0 = blockIdx.x * 32, k0 = blockIdx.y * 32;
    int tx = threadIdx.x & 31, ty = threadIdx.x >> 5;
    #pragma unroll
    for (int j = 0; j < 32; j += 8) {
        int k = k0 + ty + j, n = n0 + tx;
        t[ty + j][tx] = (n < N) ? W[(size_t)k * N + n] : 0.f;
    }
    __syncthreads();
    #pragma unroll
    for (int j = 0; j < 32; j += 8) {
        int n = n0 + ty + j, k = k0 + tx;
        if (n < N) {
            float v = t[tx][ty + j];
            __nv_bfloat16 hi = __float2bfloat16(v);
            float r = v - __bfloat162float(hi);
            out[(size_t)n * 2 * K + k]     = hi;
            out[(size_t)n * 2 * K + K + k] = __float2bfloat16(r);
        }
    }
}

// ---------------- generic mma.sync split-bf16 GEMM ----------------
// MI = 16-row fragments per warp (4 -> 128-row tile, 2 -> 64-row tile)
template<int MI, bool DOGELU, bool HASRES>
__global__ __launch_bounds__(256)
void gemm_mma_kernel(const __nv_bfloat16* __restrict__ Ab, const __nv_bfloat16* __restrict__ Bb,
                     const float* __restrict__ bias, const float* __restrict__ res,
                     float* __restrict__ C, int N, int K) {
    constexpr int MT = MI * 32;
    constexpr int ASTAGE = MT * 64;
    constexpr int STAGE = ASTAGE + 8192;
    __shared__ __align__(128) uint8_t smem[2][STAGE];
    const int tid  = threadIdx.x;
    const int lane = tid & 31, wid = tid >> 5;
    const int wm = wid >> 2, wn = wid & 3;
    const int mt = blockIdx.x, nt = blockIdx.y;
    const size_t K2 = (size_t)2 * K;
    const uint32_t sbase = smem_to_u32(smem);

    const int lrow = tid >> 2;
    const int lch  = tid & 3;
    const __nv_bfloat16* Agbase = Ab + (size_t)(mt * MT) * K2;

    const int arow = wm * (MI * 16) + (lane & 15);
    const uint32_t asw_base = (uint32_t)((arow >> 1) & 3);
    const uint32_t aoff_lm  = (uint32_t)(arow * 64);
    const int brow = wn * 32 + (lane & 7) + ((lane >> 4) << 3);
    const uint32_t bsw_base = (uint32_t)((brow >> 1) & 3);
    const uint32_t boff_lm  = (uint32_t)(brow * 64);
    const uint32_t a_chsel  = (uint32_t)(lane >> 4);
    const uint32_t b_chsel  = (uint32_t)((lane >> 3) & 1);

    float acc[MI][4][4];
    #pragma unroll
    for (int i = 0; i < MI; i++)
        #pragma unroll
        for (int j = 0; j < 4; j++)
            #pragma unroll
            for (int e = 0; e < 4; e++) acc[i][j][e] = 0.f;

    const int KC = K >> 5;
    const int NC = 3 * KC;

    auto load_chunk = [&](int c, int stg) {
        int p  = c / KC;
        int kk = c - p * KC;
        int aoff = ((p == 1) ? K : 0) + kk * 32;
        int boff = ((p == 2) ? K : 0) + kk * 32;
        uint32_t sA = sbase + stg * STAGE;
        uint32_t sB = sA + ASTAGE;
        #pragma unroll
        for (int i = 0; i < MI / 2; i++) {
            int row = lrow + 64 * i;
            const void* g = Agbase + (size_t)row * K2 + aoff + lch * 8;
            uint32_t d = sA + row * 64 + (((uint32_t)lch ^ ((uint32_t)(row >> 1) & 3)) << 4);
            cp_async16(d, g);
        }
        #pragma unroll
        for (int i = 0; i < 2; i++) {
            int row = lrow + 64 * i;
            int gn = nt * 128 + row;
            if (gn >= N) gn = N - 1;
            const void* g = Bb + (size_t)gn * K2 + boff + lch * 8;
            uint32_t d = sB + row * 64 + (((uint32_t)lch ^ ((uint32_t)(row >> 1) & 3)) << 4);
            cp_async16(d, g);
        }
        cp_commit();
    };

    load_chunk(0, 0);

    for (int c = 0; c < NC; c++) {
        int stg = c & 1;
        cp_wait0();
        __syncthreads();
        if (c + 1 < NC) load_chunk(c + 1, stg ^ 1);

        uint32_t sA = sbase + stg * STAGE;
        uint32_t sB = sA + ASTAGE;
        #pragma unroll
        for (int s = 0; s < 2; s++) {
            uint32_t aswz = ((2u * s + a_chsel) ^ asw_base) << 4;
            uint32_t bswz = ((2u * s + b_chsel) ^ bsw_base) << 4;
            uint32_t a[MI][4], b[2][4];
            #pragma unroll
            for (int mi = 0; mi < MI; mi++)
                ldsm4(a[mi][0], a[mi][1], a[mi][2], a[mi][3], sA + aoff_lm + mi * 1024 + aswz);
            #pragma unroll
            for (int j = 0; j < 2; j++)
                ldsm4(b[j][0], b[j][1], b[j][2], b[j][3], sB + boff_lm + j * 1024 + bswz);
            #pragma unroll
            for (int mi = 0; mi < MI; mi++) {
                #pragma unroll
                for (int nj = 0; nj < 4; nj++)
                    mma16816(acc[mi][nj], a[mi], &b[nj >> 1][(nj & 1) * 2]);
            }
        }
    }
    __syncthreads();

    const int rowbase = mt * MT + wm * (MI * 16) + (lane >> 2);
    const int cbase   = nt * 128 + wn * 32 + (lane & 3) * 2;
    const bool vec_ok = ((N & 1) == 0);
    float bb0[4], bb1[4];
    #pragma unroll
    for (int nj = 0; nj < 4; nj++) {
        int cc = cbase + nj * 8;
        bb0[nj] = (bias != nullptr && cc     < N) ? bias[cc]     : 0.f;
        bb1[nj] = (bias != nullptr && cc + 1 < N) ? bias[cc + 1] : 0.f;
    }
    #pragma unroll
    for (int mi = 0; mi < MI; mi++) {
        #pragma unroll
        for (int h = 0; h < 2; h++) {
            int rr = rowbase + mi * 16 + 8 * h;
            float* crow = C + (size_t)rr * N;
            const float* rrow = HASRES ? res + (size_t)rr * N : nullptr;
            #pragma unroll
            for (int nj = 0; nj < 4; nj++) {
                int cc = cbase + nj * 8;
                float v0 = acc[mi][nj][2 * h + 0] + bb0[nj];
                float v1 = acc[mi][nj][2 * h + 1] + bb1[nj];
                if (DOGELU) { v0 = gelu_f(v0); v1 = gelu_f(v1); }
                if (cc + 1 < N) {
                    if (HASRES) { v0 += rrow[cc]; v1 += rrow[cc + 1]; }
                    if (vec_ok) *(float2*)&crow[cc] = make_float2(v0, v1);
                    else { crow[cc] = v0; crow[cc + 1] = v1; }
                } else if (cc < N) {
                    if (HASRES) v0 += rrow[cc];
                    crow[cc] = v0;
                }
            }
        }
    }
}

// ---------------- attention: prep (Q/K split + V transpose split) ----------------
// grid (T/64, BHT), block 256
__global__ __launch_bounds__(256)
void attn_prep_kernel(const float* __restrict__ qkv) {
    __shared__ float vs[64][65];
    int bh = blockIdx.y;
    int b = bh / NH, h = bh % NH;
    int t0 = blockIdx.x * 64;
    int tid = threadIdx.x;
    int tl = tid >> 2;            // 0..63
    int d0 = (tid & 3) * 16;      // 0,16,32,48

    const float* src = qkv + (size_t)(b * TMAXV + t0 + tl) * (3 * EMB) + h * HD;
    __nv_bfloat16* qrow = g_Qs + ((size_t)bh * TMAXV + t0 + tl) * 128;
    __nv_bfloat16* krow = g_Ks + ((size_t)bh * TMAXV + t0 + tl) * 128;
    #pragma unroll
    for (int j = 0; j < 16; j += 4) {
        float4 qv = *(const float4*)(src + d0 + j);
        float4 kv = *(const float4*)(src + EMB + d0 + j);
        float4 vv = *(const float4*)(src + 2 * EMB + d0 + j);
        float q4[4] = {qv.x, qv.y, qv.z, qv.w};
        float k4[4] = {kv.x, kv.y, kv.z, kv.w};
        float v4[4] = {vv.x, vv.y, vv.z, vv.w};
        #pragma unroll
        for (int e = 0; e < 4; e++) {
            float q = q4[e] * 0.125f;
            __nv_bfloat16 qh = __float2bfloat16(q);
            qrow[d0 + j + e]      = qh;
            qrow[64 + d0 + j + e] = __float2bfloat16(q - __bfloat162float(qh));
            float k = k4[e];
            __nv_bfloat16 kh = __float2bfloat16(k);
            krow[d0 + j + e]      = kh;
            krow[64 + d0 + j + e] = __float2bfloat16(k - __bfloat162float(kh));
            vs[d0 + j + e][tl] = v4[e];
        }
    }
    __syncthreads();
    int d = tid >> 2;
    int tc = (tid & 3) * 16;
    __nv_bfloat16* vrow = g_Vt + ((size_t)bh * HD + d) * (2 * TMAXV);
    #pragma unroll
    for (int j = 0; j < 16; j++) {
        float v = vs[d][tc + j];
        __nv_bfloat16 hv = __float2bfloat16(v);
        vrow[t0 + tc + j]         = hv;
        vrow[TMAXV + t0 + tc + j] = __float2bfloat16(v - __bfloat162float(hv));
    }
}

// ---------------- batched attention GEMMs (S = Q@K^T lower tiles; O = P@V) ----------------
template<bool PV>
__global__ __launch_bounds__(256)
void gemm_attn_kernel() {
    __shared__ __align__(128) uint8_t smem[2][16384];
    const int bh = blockIdx.z;
    int mt, nt, Kfull, KC, N, ldc;
    const __nv_bfloat16 *Ab, *Bb;
    float* C;
    if (PV) {
        mt = blockIdx.x; nt = 0;
        Kfull = TMAXV; KC = (mt + 1) * 4; N = HD; ldc = EMB;
        Ab = g_P  + (size_t)bh * TMAXV * 2 * TMAXV;
        Bb = g_Vt + (size_t)bh * HD * 2 * TMAXV;
        C  = g_att + (size_t)(bh / NH) * TMAXV * EMB + (bh % NH) * HD;
    } else {
        int idx = blockIdx.x;
        mt = 0;
        while ((mt + 1) * (mt + 2) / 2 <= idx) mt++;
        nt = idx - mt * (mt + 1) / 2;
        Kfull = HD; KC = 2; N = TMAXV; ldc = TMAXV;
        Ab = g_Qs + (size_t)bh * TMAXV * 128;
        Bb = g_Ks + (size_t)bh * TMAXV * 128;
        C  = g_S  + (size_t)bh * TMAXV * TMAXV;
    }
    const int tid  = threadIdx.x;
    const int lane = tid & 31, wid = tid >> 5;
    const int wm = wid >> 2, wn = wid & 3;
    const size_t K2 = (size_t)2 * Kfull;
    const uint32_t sbase = smem_to_u32(smem);

    const int lrow = tid >> 2;
    const int lch  = tid & 3;
    const __nv_bfloat16* Agbase = Ab + (size_t)(mt * 128) * K2;

    const int arow = wm * 64 + (lane & 15);
    const uint32_t asw_base = (uint32_t)((arow >> 1) & 3);
    const uint32_t aoff_lm  = (uint32_t)(arow * 64);
    const int brow = wn * 32 + (lane & 7) + ((lane >> 4) << 3);
    const uint32_t bsw_base = (uint32_t)((brow >> 1) & 3);
    const uint32_t boff_lm  = (uint32_t)(brow * 64);
    const uint32_t a_chsel  = (uint32_t)(lane >> 4);
    const uint32_t b_chsel  = (uint32_t)((lane >> 3) & 1);

    float acc[4][4][4];
    #pragma unroll
    for (int i = 0; i < 4; i++)
        #pragma unroll
        for (int j = 0; j < 4; j++)
            #pragma unroll
            for (int e = 0; e < 4; e++) acc[i][j][e] = 0.f;

    const int NC = 3 * KC;

    auto load_chunk = [&](int c, int stg) {
        int p  = c / KC;
        int kk = c - p * KC;
        int aoff = ((p == 1) ? Kfull : 0) + kk * 32;
        int boff = ((p == 2) ? Kfull : 0) + kk * 32;
        uint32_t sA = sbase + stg * 16384;
        uint32_t sB = sA + 8192;
        #pragma unroll
        for (int i = 0; i < 2; i++) {
            int row = lrow + 64 * i;
            const void* g = Agbase + (size_t)row * K2 + aoff + lch * 8;
            uint32_t d = sA + row * 64 + (((uint32_t)lch ^ ((uint32_t)(row >> 1) & 3)) << 4);
            cp_async16(d, g);
        }
        #pragma unroll
        for (int i = 0; i < 2; i++) {
            int row = lrow + 64 * i;
            int gn = nt * 128 + row;
            if (gn >= N) gn = N - 1;
            const void* g = Bb + (size_t)gn * K2 + boff + lch * 8;
            uint32_t d = sB + row * 64 + (((uint32_t)lch ^ ((uint32_t)(row >> 1) & 3)) << 4);
            cp_async16(d, g);
        }
        cp_commit();
    };

    load_chunk(0, 0);

    for (int c = 0; c < NC; c++) {
        int stg = c & 1;
        cp_wait0();
        __syncthreads();
        if (c + 1 < NC) load_chunk(c + 1, stg ^ 1);

        uint32_t sA = sbase + stg * 16384;
        uint32_t sB = sA + 8192;
        #pragma unroll
        for (int s = 0; s < 2; s++) {
            uint32_t aswz = ((2u * s + a_chsel) ^ asw_base) << 4;
            uint32_t bswz = ((2u * s + b_chsel) ^ bsw_base) << 4;
            uint32_t a[4][4], b[2][4];
            #pragma unroll
            for (int mi = 0; mi < 4; mi++)
                ldsm4(a[mi][0], a[mi][1], a[mi][2], a[mi][3], sA + aoff_lm + mi * 1024 + aswz);
            #pragma unroll
            for (int j = 0; j < 2; j++)
                ldsm4(b[j][0], b[j][1], b[j][2], b[j][3], sB + boff_lm + j * 1024 + bswz);
            #pragma unroll
            for (int mi = 0; mi < 4; mi++) {
                #pragma unroll
                for (int nj = 0; nj < 4; nj++)
                    mma16816(acc[mi][nj], a[mi], &b[nj >> 1][(nj & 1) * 2]);
            }
        }
    }
    __syncthreads();

    const int rowbase = mt * 128 + wm * 64 + (lane >> 2);
    const int cbase   = nt * 128 + wn * 32 + (lane & 3) * 2;
    #pragma unroll
    for (int mi = 0; mi < 4; mi++) {
        #pragma unroll
        for (int h = 0; h < 2; h++) {
            int rr = rowbase + mi * 16 + 8 * h;
            float* crow = C + (size_t)rr * ldc;
            #pragma unroll
            for (int nj = 0; nj < 4; nj++) {
                int cc = cbase + nj * 8;
                if (cc + 1 < N)
                    *(float2*)&crow[cc] = make_float2(acc[mi][nj][2 * h], acc[mi][nj][2 * h + 1]);
                else if (cc < N)
                    crow[cc] = acc[mi][nj][2 * h];
            }
        }
    }
}

// ---------------- causal softmax (fp32 S -> split-bf16 P) ----------------
// grid (T, BHT), block 256
__global__ __launch_bounds__(256)
void softmax_kernel() {
    int q = blockIdx.x, bh = blockIdx.y;
    const float* srow = g_S + ((size_t)bh * TMAXV + q) * TMAXV;
    __nv_bfloat16* prow = g_P + ((size_t)bh * TMAXV + q) * (2 * TMAXV);
    int tid = threadIdx.x;
    __shared__ float red[8];

    float m = -1e30f;
    for (int k = tid; k <= q; k += 256) m = fmaxf(m, srow[k]);
    #pragma unroll
    for (int o = 16; o; o >>= 1) m = fmaxf(m, __shfl_xor_sync(0xffffffffu, m, o));
    if ((tid & 31) == 0) red[tid >> 5] = m;
    __syncthreads();
    m = -1e30f;
    #pragma unroll
    for (int i = 0; i < 8; i++) m = fmaxf(m, red[i]);
    __syncthreads();

    float s = 0.f;
    for (int k = tid; k <= q; k += 256) s += __expf(srow[k] - m);
    #pragma unroll
    for (int o = 16; o; o >>= 1) s += __shfl_xor_sync(0xffffffffu, s, o);
    if ((tid & 31) == 0) red[tid >> 5] = s;
    __syncthreads();
    s = 0.f;
    #pragma unroll
    for (int i = 0; i < 8; i++) s += red[i];
    float inv = 1.f / s;

    int kmax = ((q >> 7) + 1) << 7;   // pad to 128 for the PV GEMM's K bound
    for (int k = tid; k < kmax; k += 256) {
        float p = (k <= q) ? __expf(srow[k] - m) * inv : 0.f;
        __nv_bfloat16 hi = __float2bfloat16(p);
        prow[k]         = hi;
        prow[TMAXV + k] = __float2bfloat16(p - __bfloat162float(hi));
    }
}

// ---------------- host orchestration ----------------
extern "C" void kernel_launch(void* const* d_in, const int* in_sizes, int n_in,
                              void* d_out, int out_size) {
    const int*   idx         = (const int*)  d_in[0];
    const float* wte         = (const float*)d_in[1];
    const float* wpe         = (const float*)d_in[2];
    const float* ln1_w       = (const float*)d_in[3];
    const float* ln1_b       = (const float*)d_in[4];
    const float* attn_w      = (const float*)d_in[5];
    const float* attn_b      = (const float*)d_in[6];
    const float* attn_proj_w = (const float*)d_in[7];
    const float* attn_proj_b = (const float*)d_in[8];
    const float* ln2_w       = (const float*)d_in[9];
    const float* ln2_b       = (const float*)d_in[10];
    const float* fc_w        = (const float*)d_in[11];
    const float* fc_b        = (const float*)d_in[12];
    const float* fc_proj_w   = (const float*)d_in[13];
    const float* fc_proj_b   = (const float*)d_in[14];
    const float* lnf_w       = (const float*)d_in[15];
    const float* lnf_b       = (const float*)d_in[16];

    float *x, *h, *qkvb, *attb, *mlpb;
    __nv_bfloat16 *abf, *wbf, *wtebf;
    cudaGetSymbolAddress((void**)&x,    g_x);
    cudaGetSymbolAddress((void**)&h,    g_h);
    cudaGetSymbolAddress((void**)&qkvb, g_qkv);
    cudaGetSymbolAddress((void**)&attb, g_att);
    cudaGetSymbolAddress((void**)&mlpb, g_mlp);
    cudaGetSymbolAddress((void**)&abf,  g_abf);
    cudaGetSymbolAddress((void**)&wbf,  g_wbf);
    cudaGetSymbolAddress((void**)&wtebf,g_wtebf);

    embed_kernel<<<ROWS, 256>>>(idx, wte, wpe, x);

    for (int l = 0; l < NL; l++) {
        // --- attention block ---
        ln_kernel<<<ROWS, 256>>>(x, ln1_w + l * EMB, ln1_b + l * EMB, h);
        conva_kernel<<<ROWS, 256>>>(h, abf, EMB);
        convw_kernel<<<dim3((3*EMB)/32, EMB/32), 256>>>(attn_w + (size_t)l * EMB * 3 * EMB, wbf, EMB, 3*EMB);
        gemm_mma_kernel<4,false,false><<<dim3(16, 18), 256>>>(
            abf, wbf, attn_b + (size_t)l * 3 * EMB, nullptr, qkvb, 3*EMB, EMB);

        attn_prep_kernel<<<dim3(TMAXV/64, BHT), 256>>>(qkvb);
        gemm_attn_kernel<false><<<dim3(36, 1, BHT), 256>>>();
        softmax_kernel<<<dim3(TMAXV, BHT), 256>>>();
        gemm_attn_kernel<true><<<dim3(8, 1, BHT), 256>>>();

        conva_kernel<<<ROWS, 256>>>(attb, abf, EMB);
        convw_kernel<<<dim3(EMB/32, EMB/32), 256>>>(attn_proj_w + (size_t)l * EMB * EMB, wbf, EMB, EMB);
        gemm_mma_kernel<2,false,true><<<dim3(32, 6), 256>>>(
            abf, wbf, attn_proj_b + (size_t)l * EMB, x, x, EMB, EMB);

        // --- mlp block ---
        ln_kernel<<<ROWS, 256>>>(x, ln2_w + l * EMB, ln2_b + l * EMB, h);
        conva_kernel<<<ROWS, 256>>>(h, abf, EMB);
        convw_kernel<<<dim3((4*EMB)/32, EMB/32), 256>>>(fc_w + (size_t)l * EMB * 4 * EMB, wbf, EMB, 4*EMB);
        gemm_mma_kernel<4,true,false><<<dim3(16, 24), 256>>>(
            abf, wbf, fc_b + (size_t)l * 4 * EMB, nullptr, mlpb, 4*EMB, EMB);

        conva_kernel<<<ROWS, 256>>>(mlpb, abf, 4*EMB);
        convw_kernel<<<dim3(EMB/32, (4*EMB)/32), 256>>>(fc_proj_w + (size_t)l * 4 * EMB * EMB, wbf, 4*EMB, EMB);
        gemm_mma_kernel<2,false,true><<<dim3(32, 6), 256>>>(
            abf, wbf, fc_proj_b + (size_t)l * EMB, x, x, EMB, 4*EMB);
    }

    ln_kernel<<<ROWS, 256>>>(x, lnf_w, lnf_b, h);
    conva_kernel<<<ROWS, 256>>>(h, abf, EMB);
    conva_kernel<<<VOC, 256>>>(wte, wtebf, EMB);
    gemm_mma_kernel<4,false,false><<<dim3(16, (VOC + 127) / 128), 256>>>(
        abf, wtebf, nullptr, nullptr, (float*)d_out, VOC, EMB);
}

// round 7
// speedup vs baseline: 2.2641x; 1.0383x over previous
#include <cuda_runtime.h>
#include <cuda_bf16.h>
#include <cstdint>
#include <math.h>

#define TMAXV 1024
#define BATCH 2
#define EMB   768
#define NH    12
#define HD    64
#define NL    12
#define VOC   50257
#define ROWS  (BATCH*TMAXV)   // 2048
#define BHT   (BATCH*NH)      // 24

// ---------------- scratch (device globals, no allocation) ----------------
__device__ __align__(256) float g_x  [ROWS*EMB];
__device__ __align__(256) float g_qkv[ROWS*3*EMB];
__device__ __align__(256) __nv_bfloat16 g_abf [ROWS*2*EMB];            // split activations K=768
__device__ __align__(256) __nv_bfloat16 g_mbf [ROWS*2*4*EMB];          // split mlp hidden K=3072
__device__ __align__(256) __nv_bfloat16 g_wbf [3*EMB*2*4*EMB];         // split weights
__device__ __align__(256) __nv_bfloat16 g_wtebf[(size_t)VOC*2*EMB];
// attention scratch
__device__ __align__(256) __nv_bfloat16 g_Qs[(size_t)BHT*TMAXV*2*HD];
__device__ __align__(256) __nv_bfloat16 g_Ks[(size_t)BHT*TMAXV*2*HD];
__device__ __align__(256) __nv_bfloat16 g_Vt[(size_t)BHT*HD*2*TMAXV];
__device__ __align__(256) float         g_S [(size_t)BHT*TMAXV*TMAXV];
__device__ __align__(256) __nv_bfloat16 g_P [(size_t)BHT*TMAXV*2*TMAXV];

// ======================= helpers =======================
__device__ __forceinline__ uint32_t smem_to_u32(const void* p) {
    uint32_t a;
    asm("{ .reg .u64 t; cvta.to.shared.u64 t, %1; cvt.u32.u64 %0, t; }" : "=r"(a) : "l"(p));
    return a;
}
__device__ __forceinline__ void cp_async16(uint32_t saddr, const void* gaddr) {
    asm volatile("cp.async.cg.shared.global [%0], [%1], 16;" :: "r"(saddr), "l"(gaddr));
}
__device__ __forceinline__ void cp_commit() { asm volatile("cp.async.commit_group;"); }
__device__ __forceinline__ void cp_wait0()  { asm volatile("cp.async.wait_group 0;"); }
__device__ __forceinline__ void ldsm4(uint32_t& r0, uint32_t& r1, uint32_t& r2, uint32_t& r3, uint32_t addr) {
    asm volatile("ldmatrix.sync.aligned.m8n8.x4.shared.b16 {%0,%1,%2,%3}, [%4];"
        : "=r"(r0), "=r"(r1), "=r"(r2), "=r"(r3) : "r"(addr));
}
__device__ __forceinline__ void mma16816(float* d, const uint32_t* a, const uint32_t* b) {
    asm volatile("mma.sync.aligned.m16n8k16.row.col.f32.bf16.bf16.f32 "
        "{%0,%1,%2,%3}, {%4,%5,%6,%7}, {%8,%9}, {%0,%1,%2,%3};"
        : "+f"(d[0]), "+f"(d[1]), "+f"(d[2]), "+f"(d[3])
        : "r"(a[0]), "r"(a[1]), "r"(a[2]), "r"(a[3]), "r"(b[0]), "r"(b[1]));
}
__device__ __forceinline__ float gelu_f(float v) {
    float u = 0.7978845608028654f * (v + 0.044715f * v * v * v);
    return 0.5f * v * (1.f + tanhf(u));
}
__device__ __forceinline__ void splitf(float v, __nv_bfloat16& h, __nv_bfloat16& l) {
    h = __float2bfloat16(v);
    l = __float2bfloat16(v - __bfloat162float(h));
}
__device__ __forceinline__ uint32_t packbf(__nv_bfloat16 a, __nv_bfloat16 b) {
    return ((uint32_t)__bfloat16_as_ushort(b) << 16) | (uint32_t)__bfloat16_as_ushort(a);
}

// ---------------- embedding ----------------
__global__ void embed_kernel(const int* __restrict__ idx, const float* __restrict__ wte,
                             const float* __restrict__ wpe, float* __restrict__ x) {
    int row = blockIdx.x;
    int t   = row % TMAXV;
    int tok = idx[row];
    const float* we = wte + (size_t)tok * EMB;
    const float* pe = wpe + (size_t)t   * EMB;
    float* xr = x + (size_t)row * EMB;
    for (int e = threadIdx.x; e < EMB; e += blockDim.x)
        xr[e] = we[e] + pe[e];
}

// ---------------- fused layernorm + split-bf16 ----------------
__global__ __launch_bounds__(256)
void ln_split_kernel(const float* __restrict__ x, const float* __restrict__ w,
                     const float* __restrict__ b, __nv_bfloat16* __restrict__ out) {
    int row = blockIdx.x;
    const float* xr = x + (size_t)row * EMB;
    int tid = threadIdx.x;
    float v0 = xr[tid], v1 = xr[tid + 256], v2 = xr[tid + 512];
    float s  = v0 + v1 + v2;
    float sq = v0*v0 + v1*v1 + v2*v2;
    __shared__ float sh_s[8], sh_q[8];
    #pragma unroll
    for (int o = 16; o; o >>= 1) {
        s  += __shfl_xor_sync(0xffffffffu, s,  o);
        sq += __shfl_xor_sync(0xffffffffu, sq, o);
    }
    if ((tid & 31) == 0) { sh_s[tid >> 5] = s; sh_q[tid >> 5] = sq; }
    __syncthreads();
    s = 0.f; sq = 0.f;
    #pragma unroll
    for (int i = 0; i < 8; i++) { s += sh_s[i]; sq += sh_q[i]; }
    float mean = s * (1.f / EMB);
    float var  = sq * (1.f / EMB) - mean * mean;
    float rstd = rsqrtf(var + 1e-5f);
    if (tid < 192) {
        int k = tid * 4;
        float4 xv = *(const float4*)(xr + k);
        float4 wv = *(const float4*)(w + k);
        float4 bv = *(const float4*)(b + k);
        float y0 = (xv.x - mean) * rstd * wv.x + bv.x;
        float y1 = (xv.y - mean) * rstd * wv.y + bv.y;
        float y2 = (xv.z - mean) * rstd * wv.z + bv.z;
        float y3 = (xv.w - mean) * rstd * wv.w + bv.w;
        __nv_bfloat16 h0,l0,h1,l1,h2,l2,h3,l3;
        splitf(y0,h0,l0); splitf(y1,h1,l1); splitf(y2,h2,l2); splitf(y3,h3,l3);
        __nv_bfloat16* orow = out + (size_t)row * (2*EMB);
        *(uint2*)(orow + k)       = make_uint2(packbf(h0,h1), packbf(h2,h3));
        *(uint2*)(orow + EMB + k) = make_uint2(packbf(l0,l1), packbf(l2,l3));
    }
}

// ---------------- vectorized split conversions ----------------
// [M,K] f32 -> [M,2K] bf16 (hi|lo)
__global__ __launch_bounds__(256)
void conva_kernel(const float* __restrict__ in, __nv_bfloat16* __restrict__ out, int K) {
    int row = blockIdx.x;
    const float* ir = in + (size_t)row * K;
    __nv_bfloat16* orow = out + (size_t)row * 2 * K;
    for (int k = threadIdx.x * 4; k < K; k += 1024) {
        float4 v = *(const float4*)(ir + k);
        __nv_bfloat16 h0,l0,h1,l1,h2,l2,h3,l3;
        splitf(v.x,h0,l0); splitf(v.y,h1,l1); splitf(v.z,h2,l2); splitf(v.w,h3,l3);
        *(uint2*)(orow + k)     = make_uint2(packbf(h0,h1), packbf(h2,h3));
        *(uint2*)(orow + K + k) = make_uint2(packbf(l0,l1), packbf(l2,l3));
    }
}

// weights: [K,N] f32 -> [N,2K] bf16 (transpose+split). K,N multiples of 64.
__global__ __launch_bounds__(256)
void convw_kernel(const float* __restrict__ W, __nv_bfloat16* __restrict__ out, int K, int N) {
    __shared__ float t[64][68];
    int n0 = blockIdx.x * 64, k0 = blockIdx.y * 64;
    int tid = threadIdx.x;
    int c4 = tid & 15;        // float4 column group
    int r  = tid >> 4;        // 0..15
    #pragma unroll
    for (int j = 0; j < 64; j += 16) {
        int k = k0 + r + j;
        float4 v = *(const float4*)(W + (size_t)k * N + n0 + c4 * 4);
        t[r + j][c4*4+0] = v.x; t[r + j][c4*4+1] = v.y;
        t[r + j][c4*4+2] = v.z; t[r + j][c4*4+3] = v.w;
    }
    __syncthreads();
    #pragma unroll
    for (int i = 0; i < 2; i++) {
        int id = tid + 256 * i;
        int n  = id >> 3;
        int kk = (id & 7) * 8;
        uint32_t hp[4], lp[4];
        #pragma unroll
        for (int j = 0; j < 4; j++) {
            __nv_bfloat16 ha,la,hb,lb;
            splitf(t[kk + 2*j    ][n], ha, la);
            splitf(t[kk + 2*j + 1][n], hb, lb);
            hp[j] = packbf(ha, hb);
            lp[j] = packbf(la, lb);
        }
        size_t base = (size_t)(n0 + n) * 2 * K + k0 + kk;
        *(uint4*)(out + base)     = make_uint4(hp[0], hp[1], hp[2], hp[3]);
        *(uint4*)(out + base + K) = make_uint4(lp[0], lp[1], lp[2], lp[3]);
    }
}

// ---------------- generic mma.sync split-bf16 GEMM ----------------
// OUT: 0 = fp32 C[M,N]; 1 = split-bf16 C[M,2N]
template<int MI, bool DOGELU, bool HASRES, int OUT>
__global__ __launch_bounds__(256)
void gemm_mma_kernel(const __nv_bfloat16* __restrict__ Ab, const __nv_bfloat16* __restrict__ Bb,
                     const float* __restrict__ bias, const float* __restrict__ res,
                     void* __restrict__ Cv, int N, int K) {
    constexpr int MT = MI * 32;
    constexpr int ASTAGE = MT * 64;
    constexpr int STAGE = ASTAGE + 8192;
    __shared__ __align__(128) uint8_t smem[2][STAGE];
    const int tid  = threadIdx.x;
    const int lane = tid & 31, wid = tid >> 5;
    const int wm = wid >> 2, wn = wid & 3;
    const int mt = blockIdx.x, nt = blockIdx.y;
    const size_t K2 = (size_t)2 * K;
    const uint32_t sbase = smem_to_u32(smem);

    const int lrow = tid >> 2;
    const int lch  = tid & 3;
    const __nv_bfloat16* Agbase = Ab + (size_t)(mt * MT) * K2;

    const int arow = wm * (MI * 16) + (lane & 15);
    const uint32_t asw_base = (uint32_t)((arow >> 1) & 3);
    const uint32_t aoff_lm  = (uint32_t)(arow * 64);
    const int brow = wn * 32 + (lane & 7) + ((lane >> 4) << 3);
    const uint32_t bsw_base = (uint32_t)((brow >> 1) & 3);
    const uint32_t boff_lm  = (uint32_t)(brow * 64);
    const uint32_t a_chsel  = (uint32_t)(lane >> 4);
    const uint32_t b_chsel  = (uint32_t)((lane >> 3) & 1);

    float acc[MI][4][4];
    #pragma unroll
    for (int i = 0; i < MI; i++)
        #pragma unroll
        for (int j = 0; j < 4; j++)
            #pragma unroll
            for (int e = 0; e < 4; e++) acc[i][j][e] = 0.f;

    const int KC = K >> 5;
    const int NC = 3 * KC;

    auto load_chunk = [&](int c, int stg) {
        int p  = c / KC;
        int kk = c - p * KC;
        int aoff = ((p == 1) ? K : 0) + kk * 32;
        int boff = ((p == 2) ? K : 0) + kk * 32;
        uint32_t sA = sbase + stg * STAGE;
        uint32_t sB = sA + ASTAGE;
        #pragma unroll
        for (int i = 0; i < MI / 2; i++) {
            int row = lrow + 64 * i;
            const void* g = Agbase + (size_t)row * K2 + aoff + lch * 8;
            uint32_t d = sA + row * 64 + (((uint32_t)lch ^ ((uint32_t)(row >> 1) & 3)) << 4);
            cp_async16(d, g);
        }
        #pragma unroll
        for (int i = 0; i < 2; i++) {
            int row = lrow + 64 * i;
            int gn = nt * 128 + row;
            if (gn >= N) gn = N - 1;
            const void* g = Bb + (size_t)gn * K2 + boff + lch * 8;
            uint32_t d = sB + row * 64 + (((uint32_t)lch ^ ((uint32_t)(row >> 1) & 3)) << 4);
            cp_async16(d, g);
        }
        cp_commit();
    };

    load_chunk(0, 0);

    for (int c = 0; c < NC; c++) {
        int stg = c & 1;
        cp_wait0();
        __syncthreads();
        if (c + 1 < NC) load_chunk(c + 1, stg ^ 1);

        uint32_t sA = sbase + stg * STAGE;
        uint32_t sB = sA + ASTAGE;
        #pragma unroll
        for (int s = 0; s < 2; s++) {
            uint32_t aswz = ((2u * s + a_chsel) ^ asw_base) << 4;
            uint32_t bswz = ((2u * s + b_chsel) ^ bsw_base) << 4;
            uint32_t a[MI][4], b[2][4];
            #pragma unroll
            for (int mi = 0; mi < MI; mi++)
                ldsm4(a[mi][0], a[mi][1], a[mi][2], a[mi][3], sA + aoff_lm + mi * 1024 + aswz);
            #pragma unroll
            for (int j = 0; j < 2; j++)
                ldsm4(b[j][0], b[j][1], b[j][2], b[j][3], sB + boff_lm + j * 1024 + bswz);
            #pragma unroll
            for (int mi = 0; mi < MI; mi++) {
                #pragma unroll
                for (int nj = 0; nj < 4; nj++)
                    mma16816(acc[mi][nj], a[mi], &b[nj >> 1][(nj & 1) * 2]);
            }
        }
    }
    __syncthreads();

    const int rowbase = mt * MT + wm * (MI * 16) + (lane >> 2);
    const int cbase   = nt * 128 + wn * 32 + (lane & 3) * 2;
    float bb0[4], bb1[4];
    #pragma unroll
    for (int nj = 0; nj < 4; nj++) {
        int cc = cbase + nj * 8;
        bb0[nj] = (bias != nullptr && cc     < N) ? bias[cc]     : 0.f;
        bb1[nj] = (bias != nullptr && cc + 1 < N) ? bias[cc + 1] : 0.f;
    }
    if (OUT == 0) {
        float* C = (float*)Cv;
        const bool vec_ok = ((N & 1) == 0);
        #pragma unroll
        for (int mi = 0; mi < MI; mi++) {
            #pragma unroll
            for (int h = 0; h < 2; h++) {
                int rr = rowbase + mi * 16 + 8 * h;
                float* crow = C + (size_t)rr * N;
                const float* rrow = HASRES ? res + (size_t)rr * N : nullptr;
                #pragma unroll
                for (int nj = 0; nj < 4; nj++) {
                    int cc = cbase + nj * 8;
                    float v0 = acc[mi][nj][2 * h + 0] + bb0[nj];
                    float v1 = acc[mi][nj][2 * h + 1] + bb1[nj];
                    if (DOGELU) { v0 = gelu_f(v0); v1 = gelu_f(v1); }
                    if (cc + 1 < N) {
                        if (HASRES) { v0 += rrow[cc]; v1 += rrow[cc + 1]; }
                        if (vec_ok) *(float2*)&crow[cc] = make_float2(v0, v1);
                        else { crow[cc] = v0; crow[cc + 1] = v1; }
                    } else if (cc < N) {
                        if (HASRES) v0 += rrow[cc];
                        crow[cc] = v0;
                    }
                }
            }
        }
    } else {
        __nv_bfloat16* Cb = (__nv_bfloat16*)Cv;
        #pragma unroll
        for (int mi = 0; mi < MI; mi++) {
            #pragma unroll
            for (int h = 0; h < 2; h++) {
                int rr = rowbase + mi * 16 + 8 * h;
                __nv_bfloat16* crow = Cb + (size_t)rr * 2 * N;
                #pragma unroll
                for (int nj = 0; nj < 4; nj++) {
                    int cc = cbase + nj * 8;
                    if (cc + 1 < N) {
                        float v0 = acc[mi][nj][2 * h + 0] + bb0[nj];
                        float v1 = acc[mi][nj][2 * h + 1] + bb1[nj];
                        if (DOGELU) { v0 = gelu_f(v0); v1 = gelu_f(v1); }
                        __nv_bfloat16 h0,l0,h1,l1;
                        splitf(v0,h0,l0); splitf(v1,h1,l1);
                        *(uint32_t*)&crow[cc]     = packbf(h0, h1);
                        *(uint32_t*)&crow[N + cc] = packbf(l0, l1);
                    }
                }
            }
        }
    }
}

// ---------------- attention prep (Q/K split + V transpose split) ----------------
__global__ __launch_bounds__(256)
void attn_prep_kernel(const float* __restrict__ qkv) {
    __shared__ float vs[64][65];
    int bh = blockIdx.y;
    int b = bh / NH, h = bh % NH;
    int t0 = blockIdx.x * 64;
    int tid = threadIdx.x;
    int tl = tid >> 2;
    int d0 = (tid & 3) * 16;

    const float* src = qkv + (size_t)(b * TMAXV + t0 + tl) * (3 * EMB) + h * HD;
    __nv_bfloat16* qrow = g_Qs + ((size_t)bh * TMAXV + t0 + tl) * 128;
    __nv_bfloat16* krow = g_Ks + ((size_t)bh * TMAXV + t0 + tl) * 128;
    #pragma unroll
    for (int j = 0; j < 16; j += 4) {
        float4 qv = *(const float4*)(src + d0 + j);
        float4 kv = *(const float4*)(src + EMB + d0 + j);
        float4 vv = *(const float4*)(src + 2 * EMB + d0 + j);
        __nv_bfloat16 h0,l0,h1,l1,h2,l2,h3,l3;
        splitf(qv.x*0.125f,h0,l0); splitf(qv.y*0.125f,h1,l1);
        splitf(qv.z*0.125f,h2,l2); splitf(qv.w*0.125f,h3,l3);
        *(uint2*)(qrow + d0 + j)      = make_uint2(packbf(h0,h1), packbf(h2,h3));
        *(uint2*)(qrow + 64 + d0 + j) = make_uint2(packbf(l0,l1), packbf(l2,l3));
        splitf(kv.x,h0,l0); splitf(kv.y,h1,l1); splitf(kv.z,h2,l2); splitf(kv.w,h3,l3);
        *(uint2*)(krow + d0 + j)      = make_uint2(packbf(h0,h1), packbf(h2,h3));
        *(uint2*)(krow + 64 + d0 + j) = make_uint2(packbf(l0,l1), packbf(l2,l3));
        vs[d0 + j + 0][tl] = vv.x; vs[d0 + j + 1][tl] = vv.y;
        vs[d0 + j + 2][tl] = vv.z; vs[d0 + j + 3][tl] = vv.w;
    }
    __syncthreads();
    int d = tid >> 2;
    int tc = (tid & 3) * 16;
    __nv_bfloat16* vrow = g_Vt + ((size_t)bh * HD + d) * (2 * TMAXV);
    #pragma unroll
    for (int j = 0; j < 16; j += 4) {
        __nv_bfloat16 h0,l0,h1,l1,h2,l2,h3,l3;
        splitf(vs[d][tc + j + 0],h0,l0); splitf(vs[d][tc + j + 1],h1,l1);
        splitf(vs[d][tc + j + 2],h2,l2); splitf(vs[d][tc + j + 3],h3,l3);
        *(uint2*)(vrow + t0 + tc + j)         = make_uint2(packbf(h0,h1), packbf(h2,h3));
        *(uint2*)(vrow + TMAXV + t0 + tc + j) = make_uint2(packbf(l0,l1), packbf(l2,l3));
    }
}

// ---------------- batched attention GEMMs ----------------
template<bool PV>
__global__ __launch_bounds__(256)
void gemm_attn_kernel() {
    __shared__ __align__(128) uint8_t smem[2][16384];
    const int bh = blockIdx.z;
    int mt, nt, Kfull, KC, N;
    const __nv_bfloat16 *Ab, *Bb;
    float* C = nullptr;
    if (PV) {
        mt = blockIdx.x; nt = 0;
        Kfull = TMAXV; KC = (mt + 1) * 4; N = HD;
        Ab = g_P  + (size_t)bh * TMAXV * 2 * TMAXV;
        Bb = g_Vt + (size_t)bh * HD * 2 * TMAXV;
    } else {
        int idx = blockIdx.x;
        mt = 0;
        while ((mt + 1) * (mt + 2) / 2 <= idx) mt++;
        nt = idx - mt * (mt + 1) / 2;
        Kfull = HD; KC = 2; N = TMAXV;
        Ab = g_Qs + (size_t)bh * TMAXV * 128;
        Bb = g_Ks + (size_t)bh * TMAXV * 128;
        C  = g_S  + (size_t)bh * TMAXV * TMAXV;
    }
    const int tid  = threadIdx.x;
    const int lane = tid & 31, wid = tid >> 5;
    const int wm = wid >> 2, wn = wid & 3;
    const size_t K2 = (size_t)2 * Kfull;
    const uint32_t sbase = smem_to_u32(smem);

    const int lrow = tid >> 2;
    const int lch  = tid & 3;
    const __nv_bfloat16* Agbase = Ab + (size_t)(mt * 128) * K2;

    const int arow = wm * 64 + (lane & 15);
    const uint32_t asw_base = (uint32_t)((arow >> 1) & 3);
    const uint32_t aoff_lm  = (uint32_t)(arow * 64);
    const int brow = wn * 32 + (lane & 7) + ((lane >> 4) << 3);
    const uint32_t bsw_base = (uint32_t)((brow >> 1) & 3);
    const uint32_t boff_lm  = (uint32_t)(brow * 64);
    const uint32_t a_chsel  = (uint32_t)(lane >> 4);
    const uint32_t b_chsel  = (uint32_t)((lane >> 3) & 1);

    float acc[4][4][4];
    #pragma unroll
    for (int i = 0; i < 4; i++)
        #pragma unroll
        for (int j = 0; j < 4; j++)
            #pragma unroll
            for (int e = 0; e < 4; e++) acc[i][j][e] = 0.f;

    const int NC = 3 * KC;

    auto load_chunk = [&](int c, int stg) {
        int p  = c / KC;
        int kk = c - p * KC;
        int aoff = ((p == 1) ? Kfull : 0) + kk * 32;
        int boff = ((p == 2) ? Kfull : 0) + kk * 32;
        uint32_t sA = sbase + stg * 16384;
        uint32_t sB = sA + 8192;
        #pragma unroll
        for (int i = 0; i < 2; i++) {
            int row = lrow + 64 * i;
            const void* g = Agbase + (size_t)row * K2 + aoff + lch * 8;
            uint32_t d = sA + row * 64 + (((uint32_t)lch ^ ((uint32_t)(row >> 1) & 3)) << 4);
            cp_async16(d, g);
        }
        #pragma unroll
        for (int i = 0; i < 2; i++) {
            int row = lrow + 64 * i;
            int gn = nt * 128 + row;
            if (gn >= N) gn = N - 1;
            const void* g = Bb + (size_t)gn * K2 + boff + lch * 8;
            uint32_t d = sB + row * 64 + (((uint32_t)lch ^ ((uint32_t)(row >> 1) & 3)) << 4);
            cp_async16(d, g);
        }
        cp_commit();
    };

    load_chunk(0, 0);

    for (int c = 0; c < NC; c++) {
        int stg = c & 1;
        cp_wait0();
        __syncthreads();
        if (c + 1 < NC) load_chunk(c + 1, stg ^ 1);

        uint32_t sA = sbase + stg * 16384;
        uint32_t sB = sA + 8192;
        #pragma unroll
        for (int s = 0; s < 2; s++) {
            uint32_t aswz = ((2u * s + a_chsel) ^ asw_base) << 4;
            uint32_t bswz = ((2u * s + b_chsel) ^ bsw_base) << 4;
            uint32_t a[4][4], b[2][4];
            #pragma unroll
            for (int mi = 0; mi < 4; mi++)
                ldsm4(a[mi][0], a[mi][1], a[mi][2], a[mi][3], sA + aoff_lm + mi * 1024 + aswz);
            #pragma unroll
            for (int j = 0; j < 2; j++)
                ldsm4(b[j][0], b[j][1], b[j][2], b[j][3], sB + boff_lm + j * 1024 + bswz);
            #pragma unroll
            for (int mi = 0; mi < 4; mi++) {
                #pragma unroll
                for (int nj = 0; nj < 4; nj++)
                    mma16816(acc[mi][nj], a[mi], &b[nj >> 1][(nj & 1) * 2]);
            }
        }
    }
    __syncthreads();

    const int rowbase = mt * 128 + wm * 64 + (lane >> 2);
    const int cbase   = nt * 128 + wn * 32 + (lane & 3) * 2;
    if (PV) {
        // write split bf16 straight into g_abf (proj GEMM input): [token row][2*768]
        // N = 64: only columns cc < N are valid (warps wn>=2 computed clamp-garbage)
        int b_ = bh / NH, h_ = bh % NH;
        #pragma unroll
        for (int mi = 0; mi < 4; mi++) {
            #pragma unroll
            for (int h = 0; h < 2; h++) {
                int rr = rowbase + mi * 16 + 8 * h;
                __nv_bfloat16* orow = g_abf + (size_t)(b_ * TMAXV + rr) * (2*EMB) + h_ * HD;
                #pragma unroll
                for (int nj = 0; nj < 4; nj++) {
                    int cc = cbase + nj * 8;   // even
                    if (cc < N) {              // <-- restored guard (R6 bug)
                        float v0 = acc[mi][nj][2 * h + 0];
                        float v1 = acc[mi][nj][2 * h + 1];
                        __nv_bfloat16 h0,l0,h1,l1;
                        splitf(v0,h0,l0); splitf(v1,h1,l1);
                        *(uint32_t*)&orow[cc]       = packbf(h0, h1);
                        *(uint32_t*)&orow[EMB + cc] = packbf(l0, l1);
                    }
                }
            }
        }
    } else {
        #pragma unroll
        for (int mi = 0; mi < 4; mi++) {
            #pragma unroll
            for (int h = 0; h < 2; h++) {
                int rr = rowbase + mi * 16 + 8 * h;
                float* crow = C + (size_t)rr * TMAXV;
                #pragma unroll
                for (int nj = 0; nj < 4; nj++) {
                    int cc = cbase + nj * 8;
                    *(float2*)&crow[cc] = make_float2(acc[mi][nj][2 * h], acc[mi][nj][2 * h + 1]);
                }
            }
        }
    }
}

// ---------------- causal softmax (S row cached in smem) ----------------
__global__ __launch_bounds__(256)
void softmax_kernel() {
    __shared__ float srow_s[TMAXV];
    __shared__ float red[8];
    int q = blockIdx.x, bh = blockIdx.y;
    const float* srow = g_S + ((size_t)bh * TMAXV + q) * TMAXV;
    __nv_bfloat16* prow = g_P + ((size_t)bh * TMAXV + q) * (2 * TMAXV);
    int tid = threadIdx.x;

    float m = -1e30f;
    for (int k = tid; k <= q; k += 256) {
        float v = srow[k];
        srow_s[k] = v;
        m = fmaxf(m, v);
    }
    #pragma unroll
    for (int o = 16; o; o >>= 1) m = fmaxf(m, __shfl_xor_sync(0xffffffffu, m, o));
    if ((tid & 31) == 0) red[tid >> 5] = m;
    __syncthreads();
    m = -1e30f;
    #pragma unroll
    for (int i = 0; i < 8; i++) m = fmaxf(m, red[i]);
    __syncthreads();

    float s = 0.f;
    for (int k = tid; k <= q; k += 256) s += __expf(srow_s[k] - m);
    #pragma unroll
    for (int o = 16; o; o >>= 1) s += __shfl_xor_sync(0xffffffffu, s, o);
    if ((tid & 31) == 0) red[tid >> 5] = s;
    __syncthreads();
    s = 0.f;
    #pragma unroll
    for (int i = 0; i < 8; i++) s += red[i];
    float inv = 1.f / s;

    int kmax = ((q >> 7) + 1) << 7;
    for (int k0 = tid * 4; k0 < kmax; k0 += 1024) {
        float p0 = (k0     <= q) ? __expf(srow_s[k0]     - m) * inv : 0.f;
        float p1 = (k0 + 1 <= q) ? __expf(srow_s[k0 + 1] - m) * inv : 0.f;
        float p2 = (k0 + 2 <= q) ? __expf(srow_s[k0 + 2] - m) * inv : 0.f;
        float p3 = (k0 + 3 <= q) ? __expf(srow_s[k0 + 3] - m) * inv : 0.f;
        __nv_bfloat16 h0,l0,h1,l1,h2,l2,h3,l3;
        splitf(p0,h0,l0); splitf(p1,h1,l1); splitf(p2,h2,l2); splitf(p3,h3,l3);
        *(uint2*)(prow + k0)         = make_uint2(packbf(h0,h1), packbf(h2,h3));
        *(uint2*)(prow + TMAXV + k0) = make_uint2(packbf(l0,l1), packbf(l2,l3));
    }
}

// ---------------- host orchestration ----------------
extern "C" void kernel_launch(void* const* d_in, const int* in_sizes, int n_in,
                              void* d_out, int out_size) {
    const int*   idx         = (const int*)  d_in[0];
    const float* wte         = (const float*)d_in[1];
    const float* wpe         = (const float*)d_in[2];
    const float* ln1_w       = (const float*)d_in[3];
    const float* ln1_b       = (const float*)d_in[4];
    const float* attn_w      = (const float*)d_in[5];
    const float* attn_b      = (const float*)d_in[6];
    const float* attn_proj_w = (const float*)d_in[7];
    const float* attn_proj_b = (const float*)d_in[8];
    const float* ln2_w       = (const float*)d_in[9];
    const float* ln2_b       = (const float*)d_in[10];
    const float* fc_w        = (const float*)d_in[11];
    const float* fc_b        = (const float*)d_in[12];
    const float* fc_proj_w   = (const float*)d_in[13];
    const float* fc_proj_b   = (const float*)d_in[14];
    const float* lnf_w       = (const float*)d_in[15];
    const float* lnf_b       = (const float*)d_in[16];

    float *x, *qkvb;
    __nv_bfloat16 *abf, *mbf, *wbf, *wtebf;
    cudaGetSymbolAddress((void**)&x,    g_x);
    cudaGetSymbolAddress((void**)&qkvb, g_qkv);
    cudaGetSymbolAddress((void**)&abf,  g_abf);
    cudaGetSymbolAddress((void**)&mbf,  g_mbf);
    cudaGetSymbolAddress((void**)&wbf,  g_wbf);
    cudaGetSymbolAddress((void**)&wtebf,g_wtebf);

    embed_kernel<<<ROWS, 256>>>(idx, wte, wpe, x);

    for (int l = 0; l < NL; l++) {
        // --- attention block ---
        ln_split_kernel<<<ROWS, 256>>>(x, ln1_w + l * EMB, ln1_b + l * EMB, abf);
        convw_kernel<<<dim3((3*EMB)/64, EMB/64), 256>>>(attn_w + (size_t)l * EMB * 3 * EMB, wbf, EMB, 3*EMB);
        gemm_mma_kernel<4,false,false,0><<<dim3(16, 18), 256>>>(
            abf, wbf, attn_b + (size_t)l * 3 * EMB, nullptr, qkvb, 3*EMB, EMB);

        attn_prep_kernel<<<dim3(TMAXV/64, BHT), 256>>>(qkvb);
        gemm_attn_kernel<false><<<dim3(36, 1, BHT), 256>>>();
        softmax_kernel<<<dim3(TMAXV, BHT), 256>>>();
        gemm_attn_kernel<true><<<dim3(8, 1, BHT), 256>>>();   // writes split into abf

        convw_kernel<<<dim3(EMB/64, EMB/64), 256>>>(attn_proj_w + (size_t)l * EMB * EMB, wbf, EMB, EMB);
        gemm_mma_kernel<2,false,true,0><<<dim3(32, 6), 256>>>(
            abf, wbf, attn_proj_b + (size_t)l * EMB, x, x, EMB, EMB);

        // --- mlp block ---
        ln_split_kernel<<<ROWS, 256>>>(x, ln2_w + l * EMB, ln2_b + l * EMB, abf);
        convw_kernel<<<dim3((4*EMB)/64, EMB/64), 256>>>(fc_w + (size_t)l * EMB * 4 * EMB, wbf, EMB, 4*EMB);
        gemm_mma_kernel<4,true,false,1><<<dim3(16, 24), 256>>>(
            abf, wbf, fc_b + (size_t)l * 4 * EMB, nullptr, mbf, 4*EMB, EMB);

        convw_kernel<<<dim3(EMB/64, (4*EMB)/64), 256>>>(fc_proj_w + (size_t)l * 4 * EMB * EMB, wbf, 4*EMB, EMB);
        gemm_mma_kernel<2,false,true,0><<<dim3(32, 6), 256>>>(
            mbf, wbf, fc_proj_b + (size_t)l * EMB, x, x, EMB, 4*EMB);
    }

    ln_split_kernel<<<ROWS, 256>>>(x, lnf_w, lnf_b, abf);
    conva_kernel<<<VOC, 256>>>(wte, wtebf, EMB);
    gemm_mma_kernel<4,false,false,0><<<dim3(16, (VOC + 127) / 128), 256>>>(
        abf, wtebf, nullptr, nullptr, (void*)d_out, VOC, EMB);
}